// round 16
// baseline (speedup 1.0000x reference)
#include <cuda_runtime.h>
#include <cuda_bf16.h>

// ---------------------------------------------------------------------------
// Global softmax (unstabilized): out[i] = exp(x[i]) / sum_j exp(x[j])
// N = 32M fp32 (128 MB).
//
// R15 post-mortem: DRAM% is pinned at ~5.65 TB/s (read) / ~5.2 TB/s (R+W)
// regardless of occupancy (61% vs 85%) and MLP (1 vs 4). Latency hiding is
// NOT the constraint; only traffic reduction + gap removal remain.
//
// R15 -> R16: single persistent one-wave kernel (888 CTAs = 148 SMs x 6),
// monotonic-epoch spin barrier between phases (graph-replay safe, no reset),
// and a 32 KB/CTA smem cache of exp(x) (~29 MB chip-wide) so phase B
// re-reads only ~99 MB instead of 128 MB.  Traffic 384 -> 355 MB.
// ---------------------------------------------------------------------------

#define NBLOCKS 888           // 148 SMs * 6 CTAs — exactly one resident wave
#define NTHREADS 256
#define NCACHE 8              // float4 iterations cached in smem per thread

__device__ float g_partials[NBLOCKS];
__device__ unsigned int g_bar = 0;   // monotonic across graph replays

__device__ __forceinline__ float block_reduce_sum(float v, float* warp_sums)
{
    #pragma unroll
    for (int off = 16; off > 0; off >>= 1)
        v += __shfl_xor_sync(0xFFFFFFFF, v, off);
    int lane = threadIdx.x & 31;
    int warp = threadIdx.x >> 5;
    if (lane == 0) warp_sums[warp] = v;
    __syncthreads();
    if (warp == 0) {
        v = (lane < NTHREADS / 32) ? warp_sums[lane] : 0.0f;
        #pragma unroll
        for (int off = 16; off > 0; off >>= 1)
            v += __shfl_xor_sync(0xFFFFFFFF, v, off);
    }
    return v;  // valid in warp 0 lane 0
}

__device__ __forceinline__ float exp_sum4(float4 v)
{
    return (__expf(v.x) + __expf(v.y)) + (__expf(v.z) + __expf(v.w));
}

__global__ __launch_bounds__(NTHREADS, 6) void softmax_fused(
    const float* __restrict__ x, float* __restrict__ out, int n4)
{
    __shared__ float4 s_cache[NCACHE * NTHREADS];   // 32 KB: exp(x) cache
    __shared__ float  s_warp[NTHREADS / 32];
    __shared__ float  s_inv;

    const float4* __restrict__ x4 = reinterpret_cast<const float4*>(x);
    float4* __restrict__ o4 = reinterpret_cast<float4*>(out);
    const int T  = NBLOCKS * NTHREADS;
    const int i0 = blockIdx.x * NTHREADS + threadIdx.x;

    // ---------------- Phase A: sum of exp(x); cache first NCACHE iters ------
    float acc0 = 0.0f, acc1 = 0.0f, acc2 = 0.0f, acc3 = 0.0f;

    #pragma unroll
    for (int k = 0; k < NCACHE; k++) {          // i0 + 7T < n4 always (N=32M)
        float4 v = x4[i0 + k * T];
        float4 e;
        e.x = __expf(v.x); e.y = __expf(v.y);
        e.z = __expf(v.z); e.w = __expf(v.w);
        s_cache[k * NTHREADS + threadIdx.x] = e;
        acc0 += (e.x + e.y) + (e.z + e.w);
    }

    int i = i0 + NCACHE * T;
    for (; i + 3 * T < n4; i += 4 * T) {        // 4 independent loads in flight
        float4 a = x4[i];
        float4 b = x4[i + T];
        float4 c = x4[i + 2 * T];
        float4 d = x4[i + 3 * T];
        acc0 += exp_sum4(a);
        acc1 += exp_sum4(b);
        acc2 += exp_sum4(c);
        acc3 += exp_sum4(d);
    }
    for (; i < n4; i += T)
        acc0 += exp_sum4(x4[i]);

    float total = block_reduce_sum((acc0 + acc1) + (acc2 + acc3), s_warp);
    if (threadIdx.x == 0) g_partials[blockIdx.x] = total;

    // ---------------- Grid barrier (monotonic epoch, replay-safe) -----------
    __syncthreads();
    if (threadIdx.x == 0) {
        __threadfence();                                  // publish g_partials
        unsigned int ticket = atomicAdd(&g_bar, 1u);
        unsigned int target = (ticket / (unsigned)gridDim.x + 1u)
                              * (unsigned)gridDim.x;
        while (*(volatile unsigned int*)&g_bar < target) { }
        __threadfence();                                  // acquire
    }
    __syncthreads();

    // ---------------- Phase B: reduce partials, normalize -------------------
    float s = 0.0f;
    for (int k = threadIdx.x; k < NBLOCKS; k += NTHREADS)
        s += g_partials[k];
    float tot = block_reduce_sum(s, s_warp);
    if (threadIdx.x == 0) s_inv = 1.0f / tot;
    __syncthreads();
    const float inv = s_inv;

    // cached portion: no gmem read, no exp recompute
    #pragma unroll
    for (int k = 0; k < NCACHE; k++) {
        float4 e = s_cache[k * NTHREADS + threadIdx.x];
        float4 r;
        r.x = e.x * inv; r.y = e.y * inv;
        r.z = e.z * inv; r.w = e.w * inv;
        __stcs(&o4[i0 + k * T], r);
    }

    // streamed portion
    i = i0 + NCACHE * T;
    for (; i + 3 * T < n4; i += 4 * T) {
        float4 a = __ldcs(&x4[i]);
        float4 b = __ldcs(&x4[i + T]);
        float4 c = __ldcs(&x4[i + 2 * T]);
        float4 d = __ldcs(&x4[i + 3 * T]);
        float4 ra, rb, rc, rd;
        ra.x = __expf(a.x) * inv;  ra.y = __expf(a.y) * inv;
        ra.z = __expf(a.z) * inv;  ra.w = __expf(a.w) * inv;
        rb.x = __expf(b.x) * inv;  rb.y = __expf(b.y) * inv;
        rb.z = __expf(b.z) * inv;  rb.w = __expf(b.w) * inv;
        rc.x = __expf(c.x) * inv;  rc.y = __expf(c.y) * inv;
        rc.z = __expf(c.z) * inv;  rc.w = __expf(c.w) * inv;
        rd.x = __expf(d.x) * inv;  rd.y = __expf(d.y) * inv;
        rd.z = __expf(d.z) * inv;  rd.w = __expf(d.w) * inv;
        __stcs(&o4[i],         ra);
        __stcs(&o4[i + T],     rb);
        __stcs(&o4[i + 2 * T], rc);
        __stcs(&o4[i + 3 * T], rd);
    }
    for (; i < n4; i += T) {
        float4 a = __ldcs(&x4[i]);
        float4 ra;
        ra.x = __expf(a.x) * inv;  ra.y = __expf(a.y) * inv;
        ra.z = __expf(a.z) * inv;  ra.w = __expf(a.w) * inv;
        __stcs(&o4[i], ra);
    }
}

extern "C" void kernel_launch(void* const* d_in, const int* in_sizes, int n_in,
                              void* d_out, int out_size)
{
    const float* x = (const float*)d_in[0];
    float* out = (float*)d_out;
    int n = in_sizes[0];
    int n4 = n >> 2;   // N = 32M, divisible by 4

    softmax_fused<<<NBLOCKS, NTHREADS>>>(x, out, n4);
}